// round 7
// baseline (speedup 1.0000x reference)
#include <cuda_runtime.h>
#include <math.h>
#include <stdint.h>

// ---------------------------------------------------------------------------
// Problem constants
// ---------------------------------------------------------------------------
constexpr int B_  = 64;
constexpr int H_  = 1024;
constexpr int E_  = 512;
constexpr int V_  = 50257;
constexpr int KV_ = 1000;
constexpr int L_  = 512;
constexpr int G4H = 4 * H_;   // 4096

// ---------------------------------------------------------------------------
// Scratch arena (static device global: allocation-free per harness rules)
// ---------------------------------------------------------------------------
constexpr long OFF_GATES = 0;
constexpr long OFF_HB    = OFF_GATES + (long)B_ * G4H;
constexpr long OFF_U1    = OFF_HB    + (long)B_ * E_;
constexpr long OFF_U2    = OFF_U1    + (long)B_ * L_ * E_;
constexpr long OFF_SC    = OFF_U2    + (long)B_ * L_ * E_;
constexpr long OFF_HCTX  = OFF_SC    + (long)B_ * L_;
constexpr long OFF_KPART = OFF_HCTX  + (long)B_ * H_;
constexpr long OFF_BPART = OFF_KPART + (long)KV_ * E_;
constexpr long OFF_UK1   = OFF_BPART + (long)B_ * E_;
constexpr long OFF_UK2   = OFF_UK1   + (long)B_ * KV_ * E_;
constexpr long OFF_VK    = OFF_UK2   + (long)B_ * KV_ * E_;
constexpr long OFF_ACAT  = OFF_VK    + (long)B_ * KV_;
constexpr long SCRATCH_TOTAL = OFF_ACAT + (long)B_ * 2 * H_;

__device__ float g_scratch[SCRATCH_TOTAL];

// ---------------------------------------------------------------------------
// Helpers
// ---------------------------------------------------------------------------
static __device__ __forceinline__ float sigmoidf_(float x) {
    return 1.0f / (1.0f + expf(-x));
}

static __device__ __forceinline__ float to_tf32(float x) {
    uint32_t u;
    asm("cvt.rna.tf32.f32 %0, %1;" : "=r"(u) : "f"(x));
    return __uint_as_float(u);
}

static __device__ __forceinline__ float blockReduceMax(float v, float* red, int tid) {
    #pragma unroll
    for (int o = 16; o; o >>= 1) v = fmaxf(v, __shfl_xor_sync(0xffffffffu, v, o));
    if ((tid & 31) == 0) red[tid >> 5] = v;
    __syncthreads();
    int nw = blockDim.x >> 5;
    float r = red[0];
    for (int i = 1; i < nw; i++) r = fmaxf(r, red[i]);
    __syncthreads();
    return r;
}

static __device__ __forceinline__ float blockReduceSum(float v, float* red, int tid) {
    #pragma unroll
    for (int o = 16; o; o >>= 1) v += __shfl_xor_sync(0xffffffffu, v, o);
    if ((tid & 31) == 0) red[tid >> 5] = v;
    __syncthreads();
    int nw = blockDim.x >> 5;
    float r = red[0];
    for (int i = 1; i < nw; i++) r += red[i];
    __syncthreads();
    return r;
}

// ---------------------------------------------------------------------------
// K1: LSTM gates = emb[ids] @ W_ih + h @ W_hh + b_ih + b_hh
// ---------------------------------------------------------------------------
__global__ void gates_k(const int* __restrict__ ids, const float* __restrict__ emb,
                        const float* __restrict__ h, const float* __restrict__ W_ih,
                        const float* __restrict__ W_hh, const float* __restrict__ b_ih,
                        const float* __restrict__ b_hh) {
    __shared__ float xs[E_];
    __shared__ float hs[H_];
    int b = blockIdx.y;
    int tid = threadIdx.x;
    long er = (long)ids[b] * E_;
    for (int i = tid; i < E_; i += 256) xs[i] = emb[er + i];
    for (int i = tid; i < H_; i += 256) hs[i] = h[(size_t)b * H_ + i];
    __syncthreads();
    int col = blockIdx.x * 256 + tid;
    float acc = b_ih[col] + b_hh[col];
    #pragma unroll 4
    for (int e = 0; e < E_; e++) acc = fmaf(xs[e], W_ih[(size_t)e * G4H + col], acc);
    #pragma unroll 4
    for (int e = 0; e < H_; e++) acc = fmaf(hs[e], W_hh[(size_t)e * G4H + col], acc);
    g_scratch[OFF_GATES + (size_t)b * G4H + col] = acc;
}

// ---------------------------------------------------------------------------
// K2: LSTM elementwise (gate order i, f, g, o)
// ---------------------------------------------------------------------------
__global__ void lstm_k(const float* __restrict__ c_in,
                       float* __restrict__ h_t, float* __restrict__ c_t) {
    int idx = blockIdx.x * 256 + threadIdx.x;      // B*H = 65536
    int b = idx >> 10, j = idx & 1023;
    const float* g = g_scratch + OFF_GATES + (size_t)b * G4H;
    float ig = sigmoidf_(g[j]);
    float fg = sigmoidf_(g[H_ + j]);
    float gg = tanhf(g[2 * H_ + j]);
    float og = sigmoidf_(g[3 * H_ + j]);
    float ct = fg * c_in[idx] + ig * gg;
    c_t[idx] = ct;
    h_t[idx] = og * tanhf(ct);
}

// ---------------------------------------------------------------------------
// Small-M GEMM: one row per blockIdx.y (M<=64). C (scratch) = A[m,:] @ B (+C)
// ---------------------------------------------------------------------------
__global__ void smallm_k(const float* __restrict__ A, const float* __restrict__ Bm,
                         long Coff, int N, int K, int accumulate) {
    extern __shared__ float As[];
    float* C = g_scratch + Coff;
    int m = blockIdx.y;
    for (int i = threadIdx.x; i < K; i += blockDim.x) As[i] = A[(size_t)m * K + i];
    __syncthreads();
    int col = blockIdx.x * blockDim.x + threadIdx.x;
    float acc = accumulate ? C[(size_t)m * N + col] : 0.0f;
    #pragma unroll 4
    for (int kk = 0; kk < K; kk++)
        acc = fmaf(As[kk], Bm[(size_t)kk * N + col], acc);
    C[(size_t)m * N + col] = acc;
}

// ---------------------------------------------------------------------------
// Tensor-core TF32 GEMM.
// CTA tile 128(M) x 128(N), K-step 16, 8 warps each computing 64x32 via
// mma.sync.m16n8k8 tf32. 3-stage smem pipeline (exactly 48KB), operands
// staged in fragment-native layout (LDS.128 / LDS.64 frag loads), kt-XOR
// swizzle for bank-conflict-free STS/LDS.
// Epilogue: + bias[col], + rowAdd[(row/rowDiv)*N + col], tanh, + vk pad,
// store to outp (ldc) or scratch+Coff.
// Requires: K % 16 == 0, N tile-guarded, M row-guarded.
// ---------------------------------------------------------------------------
__global__ __launch_bounds__(256) void tgemm_k(
    const float* __restrict__ Ap, long Aoff,
    const float* __restrict__ Bm, int ldb,
    float* __restrict__ outp, long Coff, int ldc,
    int M, int N, int K,
    const float* __restrict__ bias,
    int useRowAdd, long rowAddOff, int rowDiv,
    int doTanh, int useVk) {

    __shared__ float sA[3][2048];   // [kt(2)][mt(8)][lane(32)][slot(4)]
    __shared__ float sB[3][2048];   // [kt(2)][nt(16)][lane(32)][slot(2)]

    const float* A = Ap ? Ap : (const float*)g_scratch + Aoff;

    const int tid  = threadIdx.x;
    const int wid  = tid >> 5;
    const int lane = tid & 31;
    const int warp_m = wid & 1;       // 2 warps over M
    const int warp_n = wid >> 1;      // 4 warps over N
    const int g   = lane >> 2;
    const int tig = lane & 3;

    const int bm = blockIdx.y * 128;
    const int bn = blockIdx.x * 128;

    float acc[4][4][4];
    #pragma unroll
    for (int i = 0; i < 4; i++)
        #pragma unroll
        for (int j = 0; j < 4; j++)
            #pragma unroll
            for (int r = 0; r < 4; r++) acc[i][j][r] = 0.0f;

    // ---- staging helpers --------------------------------------------------
    auto ldgA = [&](int k0, float* ar) {
        #pragma unroll
        for (int it = 0; it < 2; it++) {
            int item = it * 256 + tid;
            int kt = item >> 8, mt = (item >> 5) & 7, ln = item & 31;
            int row = bm + mt * 16 + (ln >> 2);
            int col = k0 + kt * 8 + (ln & 3);
            const float* base = A + (size_t)row * K + col;
            bool g0 = row < M, g1 = (row + 8) < M;
            ar[it * 4 + 0] = g0 ? base[0] : 0.0f;
            ar[it * 4 + 1] = g1 ? base[(size_t)8 * K] : 0.0f;
            ar[it * 4 + 2] = g0 ? base[4] : 0.0f;
            ar[it * 4 + 3] = g1 ? base[(size_t)8 * K + 4] : 0.0f;
        }
    };
    auto ldgB = [&](int k0, float* br) {
        #pragma unroll
        for (int it = 0; it < 4; it++) {
            int item = it * 256 + tid;
            int kt = item >> 9, nt = (item >> 5) & 15, ln = item & 31;
            int colg = bn + nt * 8 + (ln >> 2);
            int r = k0 + kt * 8 + (ln & 3);
            bool ok = colg < N;
            const float* base = Bm + (size_t)r * ldb + colg;
            br[it * 2 + 0] = ok ? base[0] : 0.0f;
            br[it * 2 + 1] = ok ? base[(size_t)4 * ldb] : 0.0f;
        }
    };
    auto stsAB = [&](int buf, const float* ar, const float* br) {
        #pragma unroll
        for (int it = 0; it < 2; it++) {
            int item = it * 256 + tid;
            int kt = item >> 8, mt = (item >> 5) & 7, ln = item & 31;
            float4 v = make_float4(to_tf32(ar[it * 4 + 0]), to_tf32(ar[it * 4 + 1]),
                                   to_tf32(ar[it * 4 + 2]), to_tf32(ar[it * 4 + 3]));
            *(float4*)&sA[buf][((kt * 8 + mt) * 32 + (ln ^ (kt << 2))) * 4] = v;
        }
        #pragma unroll
        for (int it = 0; it < 4; it++) {
            int item = it * 256 + tid;
            int kt = item >> 9, nt = (item >> 5) & 15, ln = item & 31;
            float2 v = make_float2(to_tf32(br[it * 2 + 0]), to_tf32(br[it * 2 + 1]));
            *(float2*)&sB[buf][((kt * 16 + nt) * 32 + (ln ^ (kt << 2))) * 2] = v;
        }
    };
    auto compute = [&](int buf) {
        #pragma unroll
        for (int kt = 0; kt < 2; kt++) {
            int lx = lane ^ (kt << 2);
            float2 bf[4];
            #pragma unroll
            for (int nti = 0; nti < 4; nti++)
                bf[nti] = *(const float2*)&sB[buf][((kt * 16 + (warp_n * 4 + nti)) * 32 + lx) * 2];
            #pragma unroll
            for (int mti = 0; mti < 4; mti++) {
                float4 af = *(const float4*)&sA[buf][((kt * 8 + (warp_m * 4 + mti)) * 32 + lx) * 4];
                #pragma unroll
                for (int nti = 0; nti < 4; nti++) {
                    asm volatile(
                        "mma.sync.aligned.m16n8k8.row.col.f32.tf32.tf32.f32 "
                        "{%0,%1,%2,%3}, {%4,%5,%6,%7}, {%8,%9}, {%0,%1,%2,%3};"
                        : "+f"(acc[mti][nti][0]), "+f"(acc[mti][nti][1]),
                          "+f"(acc[mti][nti][2]), "+f"(acc[mti][nti][3])
                        : "r"(__float_as_uint(af.x)), "r"(__float_as_uint(af.y)),
                          "r"(__float_as_uint(af.z)), "r"(__float_as_uint(af.w)),
                          "r"(__float_as_uint(bf[nti].x)), "r"(__float_as_uint(bf[nti].y)));
                }
            }
        }
    };

    // ---- pipeline ---------------------------------------------------------
    const int nsteps = K >> 4;     // K/16, always >= 3 here
    float arA0[8], arB0[8], arA1[8], arB1[8];

    ldgA(0, arA0);  ldgB(0, arB0);
    ldgA(16, arA1); ldgB(16, arB1);
    stsAB(0, arA0, arB0);
    ldgA(32, arA0); ldgB(32, arB0);
    __syncthreads();

    int b0 = 0, b1 = 1, b2 = 2;
    int s = 0;
    while (s < nsteps) {
        // parity q = 1: stage set 1 holds kstep s+1
        compute(b0);
        if (s + 1 < nsteps) stsAB(b1, arA1, arB1);
        if (s + 3 < nsteps) { ldgA((s + 3) << 4, arA1); ldgB((s + 3) << 4, arB1); }
        __syncthreads();
        { int t = b0; b0 = b1; b1 = b2; b2 = t; }
        s++;
        if (s >= nsteps) break;
        // parity q = 0
        compute(b0);
        if (s + 1 < nsteps) stsAB(b1, arA0, arB0);
        if (s + 3 < nsteps) { ldgA((s + 3) << 4, arA0); ldgB((s + 3) << 4, arB0); }
        __syncthreads();
        { int t = b0; b0 = b1; b1 = b2; b2 = t; }
        s++;
    }

    // ---- epilogue ---------------------------------------------------------
    float* Co = outp ? outp : (g_scratch + Coff);
    const float* raB = useRowAdd ? (const float*)g_scratch + rowAddOff : nullptr;

    #pragma unroll
    for (int mti = 0; mti < 4; mti++) {
        #pragma unroll
        for (int r = 0; r < 4; r++) {
            int row = bm + warp_m * 64 + mti * 16 + g + ((r >= 2) ? 8 : 0);
            if (row >= M) continue;
            const float* ra = raB ? raB + (size_t)(row / rowDiv) * N : nullptr;
            #pragma unroll
            for (int nti = 0; nti < 4; nti++) {
                int col = bn + warp_n * 32 + nti * 8 + tig * 2 + (r & 1);
                if (col >= N) continue;
                float v = acc[mti][nti][r];
                if (bias) v += bias[col];
                if (ra) v += ra[col];
                if (doTanh) v = tanhf(v);
                if (useVk) {
                    int kc = col - (V_ - KV_);
                    if (kc >= 0) v += g_scratch[OFF_VK + (size_t)row * KV_ + kc];
                }
                Co[(size_t)row * ldc + col] = v;
            }
        }
    }
}

// ---------------------------------------------------------------------------
// Row dot: out[m] = A[m,:K] . w + b   (warp per row). K <= 512.
// ---------------------------------------------------------------------------
__global__ void rowdot_k(long Aoff, const float* __restrict__ w,
                         const float* __restrict__ bptr, long Ooff, int M, int K) {
    __shared__ float ws[512];
    const float* A = (const float*)g_scratch + Aoff;
    float* out = g_scratch + Ooff;
    int tid = threadIdx.x;
    for (int i = tid; i < K; i += 256) ws[i] = w[i];
    __syncthreads();
    int warp = tid >> 5, lane = tid & 31;
    int row = blockIdx.x * 8 + warp;
    if (row >= M) return;
    const float* ar = A + (size_t)row * K;
    float s = 0.f;
    #pragma unroll
    for (int e = lane; e < K; e += 32) s = fmaf(ar[e], ws[e], s);
    #pragma unroll
    for (int o = 16; o; o >>= 1) s += __shfl_xor_sync(0xffffffffu, s, o);
    if (lane == 0) out[row] = s + bptr[0];
}

// ---------------------------------------------------------------------------
// softmax over L=512, in place at OFF_SC. block per b, 256 threads
// ---------------------------------------------------------------------------
__global__ void softmax_k() {
    __shared__ float red[32];
    float* row = g_scratch + OFF_SC + (size_t)blockIdx.x * L_;
    int tid = threadIdx.x;
    float v0 = row[tid], v1 = row[tid + 256];
    float m = blockReduceMax(fmaxf(v0, v1), red, tid);
    float e0 = expf(v0 - m), e1 = expf(v1 - m);
    float s = blockReduceSum(e0 + e1, red, tid);
    float inv = 1.0f / s;
    row[tid] = e0 * inv;
    row[tid + 256] = e1 * inv;
}

// ---------------------------------------------------------------------------
// h_ctx[b, col] = sum_l a[b,l] * enc[b,l,col].  grid (H/256, B)
// ---------------------------------------------------------------------------
__global__ void ctx_k(const float* __restrict__ enc) {
    __shared__ float as[L_];
    int b = blockIdx.y, tid = threadIdx.x;
    for (int i = tid; i < L_; i += 256) as[i] = g_scratch[OFF_SC + (size_t)b * L_ + i];
    __syncthreads();
    int col = blockIdx.x * 256 + tid;
    const float* ep = enc + (size_t)b * L_ * H_ + col;
    float acc = 0.f;
    #pragma unroll 4
    for (int l = 0; l < L_; l++) acc = fmaf(as[l], ep[(size_t)l * H_], acc);
    g_scratch[OFF_HCTX + (size_t)b * H_ + col] = acc;
}

// ---------------------------------------------------------------------------
// uk1[b*KV+kv, e] = tanh(bpart[b,e] + kpart[kv,e] + kb1[e])
// ---------------------------------------------------------------------------
__global__ void uk1_k(const float* __restrict__ kb1) {
    size_t idx = (size_t)blockIdx.x * 256 + threadIdx.x;   // 64*1000*512
    int e = (int)(idx & (E_ - 1));
    size_t r = idx >> 9;
    int b = (int)(r / KV_);
    int kv = (int)(r - (size_t)b * KV_);
    g_scratch[OFF_UK1 + idx] = tanhf(g_scratch[OFF_BPART + (size_t)b * E_ + e] +
                                     g_scratch[OFF_KPART + (size_t)kv * E_ + e] + kb1[e]);
}

// ---------------------------------------------------------------------------
// Acat[b, 0:2048] = cat(h_t[b], h_ctx[b])
// ---------------------------------------------------------------------------
__global__ void acat_k(const float* __restrict__ h_t) {
    int idx = blockIdx.x * 256 + threadIdx.x;   // 64*2048
    int b = idx >> 11, j = idx & 2047;
    float v = (j < H_) ? h_t[(size_t)b * H_ + j]
                       : g_scratch[OFF_HCTX + (size_t)b * H_ + (j - H_)];
    g_scratch[OFF_ACAT + idx] = v;
}

// ---------------------------------------------------------------------------
// log_softmax over V, in place on y. block per b, 1024 threads.
// ---------------------------------------------------------------------------
__global__ void logsoftmax_k(float* __restrict__ y) {
    __shared__ float red[32];
    float* row = y + (size_t)blockIdx.x * V_;
    int tid = threadIdx.x;
    float m = -INFINITY;
    for (int i = tid; i < V_; i += 1024) m = fmaxf(m, row[i]);
    m = blockReduceMax(m, red, tid);
    float s = 0.f;
    for (int i = tid; i < V_; i += 1024) s += expf(row[i] - m);
    s = blockReduceSum(s, red, tid);
    float lse = m + logf(s);
    for (int i = tid; i < V_; i += 1024) row[i] -= lse;
}

// ---------------------------------------------------------------------------
// Launch
// ---------------------------------------------------------------------------
extern "C" void kernel_launch(void* const* d_in, const int* in_sizes, int n_in,
                              void* d_out, int out_size) {
    const int*   ids  = (const int*)d_in[0];
    const float* h    = (const float*)d_in[1];
    const float* c    = (const float*)d_in[2];
    const float* k    = (const float*)d_in[3];
    const float* ctxv = (const float*)d_in[4];
    const float* enc  = (const float*)d_in[5];
    const float* emb  = (const float*)d_in[6];
    const float* W_ih = (const float*)d_in[7];
    const float* W_hh = (const float*)d_in[8];
    const float* b_ih = (const float*)d_in[9];
    const float* b_hh = (const float*)d_in[10];
    const float* aW1  = (const float*)d_in[11];
    const float* ab1  = (const float*)d_in[12];
    const float* aW2  = (const float*)d_in[13];
    const float* ab2  = (const float*)d_in[14];
    const float* aW3  = (const float*)d_in[15];
    const float* ab3  = (const float*)d_in[16];
    const float* kW1  = (const float*)d_in[17];
    const float* kb1  = (const float*)d_in[18];
    const float* kW2  = (const float*)d_in[19];
    const float* kb2  = (const float*)d_in[20];
    const float* kW3  = (const float*)d_in[21];
    const float* kb3  = (const float*)d_in[22];
    const float* alW  = (const float*)d_in[23];
    const float* alb  = (const float*)d_in[24];

    float* y   = (float*)d_out;
    float* h_t = y + (size_t)B_ * V_;
    float* c_t = h_t + (size_t)B_ * H_;

    // LSTM
    gates_k<<<dim3(G4H / 256, B_), 256>>>(ids, emb, h, W_ih, W_hh, b_ih, b_hh);
    lstm_k<<<(B_ * H_) / 256, 256>>>(c, h_t, c_t);

    // additive attention:  u1 = tanh(enc@aW1[:H] + h_t@aW1[H:2H] + ab1)
    smallm_k<<<dim3(E_ / 256, B_), 256, H_ * sizeof(float)>>>(
        h_t, aW1 + (size_t)H_ * E_, OFF_HB, E_, H_, 0);
    tgemm_k<<<dim3(E_ / 128, (B_ * L_) / 128), 256>>>(
        enc, 0, aW1, E_, nullptr, OFF_U1, E_,
        B_ * L_, E_, H_, ab1, 1, OFF_HB, L_, 1, 0);
    tgemm_k<<<dim3(E_ / 128, (B_ * L_) / 128), 256>>>(
        nullptr, OFF_U1, aW2, E_, nullptr, OFF_U2, E_,
        B_ * L_, E_, E_, ab2, 0, 0, 1, 1, 0);
    rowdot_k<<<(B_ * L_) / 8, 256>>>(OFF_U2, aW3, ab3, OFF_SC, B_ * L_, E_);
    softmax_k<<<B_, 256>>>();
    ctx_k<<<dim3(H_ / 256, B_), 256>>>(enc);

    // key attention:  uk1 = tanh([ctx,h_t]@kW1[:2H] + k@kW1[2H:] + kb1)
    smallm_k<<<dim3(E_ / 256, B_), 256, H_ * sizeof(float)>>>(
        ctxv, kW1, OFF_BPART, E_, H_, 0);
    smallm_k<<<dim3(E_ / 256, B_), 256, H_ * sizeof(float)>>>(
        h_t, kW1 + (size_t)H_ * E_, OFF_BPART, E_, H_, 1);
    tgemm_k<<<dim3(E_ / 128, (KV_ + 127) / 128), 256>>>(
        k, 0, kW1 + (size_t)2 * H_ * E_, E_, nullptr, OFF_KPART, E_,
        KV_, E_, E_, nullptr, 0, 0, 1, 0, 0);
    uk1_k<<<(B_ * KV_ * E_) / 256, 256>>>(kb1);
    tgemm_k<<<dim3(E_ / 128, (B_ * KV_) / 128), 256>>>(
        nullptr, OFF_UK1, kW2, E_, nullptr, OFF_UK2, E_,
        B_ * KV_, E_, E_, kb2, 0, 0, 1, 1, 0);
    rowdot_k<<<(B_ * KV_) / 8, 256>>>(OFF_UK2, kW3, kb3, OFF_VK, B_ * KV_, E_);

    // vocab projection + key logits + log_softmax
    acat_k<<<(B_ * 2 * H_) / 256, 256>>>(h_t);
    tgemm_k<<<dim3((V_ + 127) / 128, 1), 256>>>(
        nullptr, OFF_ACAT, alW, V_, y, 0, V_,
        B_, V_, 2 * H_, alb, 0, 0, 1, 0, 1);
    logsoftmax_k<<<B_, 1024>>>(y);
}

// round 8
// speedup vs baseline: 1.4064x; 1.4064x over previous
#include <cuda_runtime.h>
#include <math.h>
#include <stdint.h>

// ---------------------------------------------------------------------------
// Problem constants
// ---------------------------------------------------------------------------
constexpr int B_  = 64;
constexpr int H_  = 1024;
constexpr int E_  = 512;
constexpr int V_  = 50257;
constexpr int KV_ = 1000;
constexpr int L_  = 512;
constexpr int G4H = 4 * H_;   // 4096

// ---------------------------------------------------------------------------
// Scratch arena (static device global: allocation-free per harness rules)
// ---------------------------------------------------------------------------
constexpr long OFF_GATES = 0;
constexpr long OFF_HB    = OFF_GATES + (long)B_ * G4H;
constexpr long OFF_U1    = OFF_HB    + (long)B_ * E_;
constexpr long OFF_U2    = OFF_U1    + (long)B_ * L_ * E_;
constexpr long OFF_SC    = OFF_U2    + (long)B_ * L_ * E_;
constexpr long OFF_HCTX  = OFF_SC    + (long)B_ * L_;
constexpr long OFF_KPART = OFF_HCTX  + (long)B_ * H_;
constexpr long OFF_BPART = OFF_KPART + (long)KV_ * E_;
constexpr long OFF_UK1   = OFF_BPART + (long)B_ * E_;
constexpr long OFF_UK2   = OFF_UK1   + (long)B_ * KV_ * E_;
constexpr long OFF_VK    = OFF_UK2   + (long)B_ * KV_ * E_;
constexpr long OFF_ACAT  = OFF_VK    + (long)B_ * KV_;
constexpr long SCRATCH_TOTAL = OFF_ACAT + (long)B_ * 2 * H_;

__device__ __align__(16) float g_scratch[SCRATCH_TOTAL];

// ---------------------------------------------------------------------------
// Helpers
// ---------------------------------------------------------------------------
static __device__ __forceinline__ float sigmoidf_(float x) {
    return 1.0f / (1.0f + expf(-x));
}

static __device__ __forceinline__ float to_tf32(float x) {
    uint32_t u;
    asm("cvt.rna.tf32.f32 %0, %1;" : "=r"(u) : "f"(x));
    return __uint_as_float(u);
}

static __device__ __forceinline__ uint32_t smem_u32(const void* p) {
    return (uint32_t)__cvta_generic_to_shared(p);
}

static __device__ __forceinline__ void cp_async16(uint32_t dst, const void* src, int szBytes) {
    asm volatile("cp.async.cg.shared.global [%0], [%1], 16, %2;\n"
                 :: "r"(dst), "l"(src), "r"(szBytes) : "memory");
}

static __device__ __forceinline__ float blockReduceMax(float v, float* red, int tid) {
    #pragma unroll
    for (int o = 16; o; o >>= 1) v = fmaxf(v, __shfl_xor_sync(0xffffffffu, v, o));
    if ((tid & 31) == 0) red[tid >> 5] = v;
    __syncthreads();
    int nw = blockDim.x >> 5;
    float r = red[0];
    for (int i = 1; i < nw; i++) r = fmaxf(r, red[i]);
    __syncthreads();
    return r;
}

static __device__ __forceinline__ float blockReduceSum(float v, float* red, int tid) {
    #pragma unroll
    for (int o = 16; o; o >>= 1) v += __shfl_xor_sync(0xffffffffu, v, o);
    if ((tid & 31) == 0) red[tid >> 5] = v;
    __syncthreads();
    int nw = blockDim.x >> 5;
    float r = red[0];
    for (int i = 1; i < nw; i++) r += red[i];
    __syncthreads();
    return r;
}

// ---------------------------------------------------------------------------
// K1: LSTM gates = emb[ids] @ W_ih + h @ W_hh + b_ih + b_hh
// ---------------------------------------------------------------------------
__global__ void gates_k(const int* __restrict__ ids, const float* __restrict__ emb,
                        const float* __restrict__ h, const float* __restrict__ W_ih,
                        const float* __restrict__ W_hh, const float* __restrict__ b_ih,
                        const float* __restrict__ b_hh) {
    __shared__ float xs[E_];
    __shared__ float hs[H_];
    int b = blockIdx.y;
    int tid = threadIdx.x;
    long er = (long)ids[b] * E_;
    for (int i = tid; i < E_; i += 256) xs[i] = emb[er + i];
    for (int i = tid; i < H_; i += 256) hs[i] = h[(size_t)b * H_ + i];
    __syncthreads();
    int col = blockIdx.x * 256 + tid;
    float acc = b_ih[col] + b_hh[col];
    #pragma unroll 4
    for (int e = 0; e < E_; e++) acc = fmaf(xs[e], W_ih[(size_t)e * G4H + col], acc);
    #pragma unroll 4
    for (int e = 0; e < H_; e++) acc = fmaf(hs[e], W_hh[(size_t)e * G4H + col], acc);
    g_scratch[OFF_GATES + (size_t)b * G4H + col] = acc;
}

// ---------------------------------------------------------------------------
// K2: LSTM elementwise (gate order i, f, g, o)
// ---------------------------------------------------------------------------
__global__ void lstm_k(const float* __restrict__ c_in,
                       float* __restrict__ h_t, float* __restrict__ c_t) {
    int idx = blockIdx.x * 256 + threadIdx.x;      // B*H = 65536
    int b = idx >> 10, j = idx & 1023;
    const float* g = g_scratch + OFF_GATES + (size_t)b * G4H;
    float ig = sigmoidf_(g[j]);
    float fg = sigmoidf_(g[H_ + j]);
    float gg = tanhf(g[2 * H_ + j]);
    float og = sigmoidf_(g[3 * H_ + j]);
    float ct = fg * c_in[idx] + ig * gg;
    c_t[idx] = ct;
    h_t[idx] = og * tanhf(ct);
}

// ---------------------------------------------------------------------------
// Small-M GEMM: one row per blockIdx.y (M<=64). C (scratch) = A[m,:] @ B (+C)
// ---------------------------------------------------------------------------
__global__ void smallm_k(const float* __restrict__ A, const float* __restrict__ Bm,
                         long Coff, int N, int K, int accumulate) {
    extern __shared__ float As[];
    float* C = g_scratch + Coff;
    int m = blockIdx.y;
    for (int i = threadIdx.x; i < K; i += blockDim.x) As[i] = A[(size_t)m * K + i];
    __syncthreads();
    int col = blockIdx.x * blockDim.x + threadIdx.x;
    float acc = accumulate ? C[(size_t)m * N + col] : 0.0f;
    #pragma unroll 4
    for (int kk = 0; kk < K; kk++)
        acc = fmaf(As[kk], Bm[(size_t)kk * N + col], acc);
    C[(size_t)m * N + col] = acc;
}

// ---------------------------------------------------------------------------
// TF32 tensor-core GEMM with 3-stage cp.async pipeline.
// CTA tile 128x128, k-step 16, 8 warps of 64x32 (m16n8k8 mma).
// A smem: [128 rows][stride 20 floats] (20 => conflict-free frag LDS).
// B smem: [16 k][128 n] with 8-float XOR swizzle (n>>3)^(k&3).
// No cvt: HMMA.TF32 truncates mantissa in hardware.
// Requires: K%16==0, N multiple of 128, ldb%4==0, A rows 16B-aligned.
// Epilogue: + bias, + rowAdd[(row/rowDiv)*N], optional tanh.
// ---------------------------------------------------------------------------
constexpr int CA_ASTRIDE = 20;                    // floats per A row in smem
constexpr int CA_ASZ = 128 * CA_ASTRIDE;          // 2560 floats / stage
constexpr int CA_BSZ = 16 * 128;                  // 2048 floats / stage
constexpr int CA_SMEM_BYTES = 3 * (CA_ASZ + CA_BSZ) * 4;   // 55296 B

__global__ __launch_bounds__(256, 2) void tgemm_ca_k(
    const float* __restrict__ Ap, long Aoff,
    const float* __restrict__ Bm, int ldb,
    long Coff, int ldc,
    int M, int N, int K,
    const float* __restrict__ bias,
    int useRowAdd, long rowAddOff, int rowDiv,
    int doTanh) {

    extern __shared__ float smem[];
    float* Abase = smem;                     // 3 * 2560
    float* Bbase = smem + 3 * CA_ASZ;        // 3 * 2048

    const float* A = Ap ? Ap : (const float*)g_scratch + Aoff;

    const int tid  = threadIdx.x;
    const int wid  = tid >> 5;
    const int lane = tid & 31;
    const int warp_m = wid & 1;
    const int warp_n = wid >> 1;
    const int g   = lane >> 2;
    const int tig = lane & 3;

    const int bm = blockIdx.y * 128;
    const int bn = blockIdx.x * 128;
    const int nsteps = K >> 4;

    float acc[4][4][4];
    #pragma unroll
    for (int i = 0; i < 4; i++)
        #pragma unroll
        for (int j = 0; j < 4; j++)
            #pragma unroll
            for (int r = 0; r < 4; r++) acc[i][j][r] = 0.0f;

    // per-thread cp.async geometry (loop-invariant)
    const int aRow0 = tid >> 2;            // + 64 for second item
    const int aC    = (tid & 3) * 4;
    const int bK0   = tid >> 5;            // + 8 for second item
    const int bCn   = tid & 31;

    auto issue = [&](int buf, int kstep) {
        if (kstep < nsteps) {
            const int k0 = kstep << 4;
            float* Ad = Abase + buf * CA_ASZ;
            float* Bd = Bbase + buf * CA_BSZ;
            #pragma unroll
            for (int it = 0; it < 2; it++) {
                int row = aRow0 + it * 64;
                int rg = bm + row;
                int ok = rg < M;
                int rc = ok ? rg : (M - 1);
                cp_async16(smem_u32(Ad + row * CA_ASTRIDE + aC),
                           A + (size_t)rc * K + k0 + aC, ok ? 16 : 0);
            }
            #pragma unroll
            for (int it = 0; it < 2; it++) {
                int kr = bK0 + it * 8;
                uint32_t grp = (uint32_t)(bCn >> 1) ^ (uint32_t)(kr & 3);
                cp_async16(smem_u32(Bd + kr * 128 + grp * 8 + (bCn & 1) * 4),
                           Bm + (size_t)(k0 + kr) * ldb + bn + bCn * 4, 16);
            }
        }
        asm volatile("cp.async.commit_group;\n" ::: "memory");
    };

    // fragment-load constants
    int bcol[4];
    #pragma unroll
    for (int nti = 0; nti < 4; nti++)
        bcol[nti] = g + 8 * ((warp_n * 4 + nti) ^ tig);
    const int am0 = (warp_m * 64 + g) * CA_ASTRIDE;

    auto compute = [&](int buf) {
        const float* At = Abase + buf * CA_ASZ;
        const float* Bt = Bbase + buf * CA_BSZ;
        #pragma unroll
        for (int kt = 0; kt < 2; kt++) {
            const int k0 = kt * 8 + tig;
            float b0[4], b1[4];
            #pragma unroll
            for (int nti = 0; nti < 4; nti++) {
                b0[nti] = Bt[k0 * 128 + bcol[nti]];
                b1[nti] = Bt[(k0 + 4) * 128 + bcol[nti]];
            }
            #pragma unroll
            for (int mti = 0; mti < 4; mti++) {
                const float* Ar = At + am0 + mti * 16 * CA_ASTRIDE;
                float a0 = Ar[k0];
                float a1 = Ar[8 * CA_ASTRIDE + k0];
                float a2 = Ar[k0 + 4];
                float a3 = Ar[8 * CA_ASTRIDE + k0 + 4];
                #pragma unroll
                for (int nti = 0; nti < 4; nti++) {
                    asm volatile(
                        "mma.sync.aligned.m16n8k8.row.col.f32.tf32.tf32.f32 "
                        "{%0,%1,%2,%3}, {%4,%5,%6,%7}, {%8,%9}, {%0,%1,%2,%3};"
                        : "+f"(acc[mti][nti][0]), "+f"(acc[mti][nti][1]),
                          "+f"(acc[mti][nti][2]), "+f"(acc[mti][nti][3])
                        : "r"(__float_as_uint(a0)), "r"(__float_as_uint(a1)),
                          "r"(__float_as_uint(a2)), "r"(__float_as_uint(a3)),
                          "r"(__float_as_uint(b0[nti])), "r"(__float_as_uint(b1[nti])));
                }
            }
        }
    };

    // prologue: 2 stages in flight
    issue(0, 0);
    issue(1, 1);

    for (int s = 0; s < nsteps; s++) {
        asm volatile("cp.async.wait_group 1;\n" ::: "memory");
        __syncthreads();
        int nb = s + 2;
        issue(nb % 3, nb);          // overwrites stage consumed at s-1 (safe: synced at s)
        compute(s % 3);
    }

    // epilogue
    float* Co = g_scratch + Coff;
    const float* raB = useRowAdd ? (const float*)g_scratch + rowAddOff : nullptr;
    #pragma unroll
    for (int mti = 0; mti < 4; mti++) {
        #pragma unroll
        for (int r = 0; r < 4; r++) {
            int row = bm + warp_m * 64 + mti * 16 + g + ((r >= 2) ? 8 : 0);
            if (row >= M) continue;
            const float* ra = raB ? raB + (size_t)(row / rowDiv) * N : nullptr;
            #pragma unroll
            for (int nti = 0; nti < 4; nti++) {
                int col = bn + warp_n * 32 + nti * 8 + tig * 2 + (r & 1);
                float v = acc[mti][nti][r];
                if (bias) v += bias[col];
                if (ra) v += ra[col];
                if (doTanh) v = tanhf(v);
                Co[(size_t)row * ldc + col] = v;
            }
        }
    }
}

// ---------------------------------------------------------------------------
// LDG+STS TF32 GEMM (kept for the vocab projection: ldb=V breaks cp.async
// alignment). 128x128 tile, 3-stage smem pipeline, fragment-native layout.
// Epilogue adds bias + key-logit pad, stores to outp (ldc).
// ---------------------------------------------------------------------------
__global__ __launch_bounds__(256) void tgemm_ldg_k(
    long Aoff,
    const float* __restrict__ Bm, int ldb,
    float* __restrict__ outp, int ldc,
    int M, int N, int K,
    const float* __restrict__ bias, int useVk) {

    __shared__ float sA[3][2048];
    __shared__ float sB[3][2048];

    const float* A = (const float*)g_scratch + Aoff;

    const int tid  = threadIdx.x;
    const int wid  = tid >> 5;
    const int lane = tid & 31;
    const int warp_m = wid & 1;
    const int warp_n = wid >> 1;
    const int g   = lane >> 2;
    const int tig = lane & 3;

    const int bm = blockIdx.y * 128;
    const int bn = blockIdx.x * 128;

    float acc[4][4][4];
    #pragma unroll
    for (int i = 0; i < 4; i++)
        #pragma unroll
        for (int j = 0; j < 4; j++)
            #pragma unroll
            for (int r = 0; r < 4; r++) acc[i][j][r] = 0.0f;

    auto ldgA = [&](int k0, float* ar) {
        #pragma unroll
        for (int it = 0; it < 2; it++) {
            int item = it * 256 + tid;
            int kt = item >> 8, mt = (item >> 5) & 7, ln = item & 31;
            int row = bm + mt * 16 + (ln >> 2);
            int col = k0 + kt * 8 + (ln & 3);
            const float* base = A + (size_t)row * K + col;
            bool g0 = row < M, g1 = (row + 8) < M;
            ar[it * 4 + 0] = g0 ? base[0] : 0.0f;
            ar[it * 4 + 1] = g1 ? base[(size_t)8 * K] : 0.0f;
            ar[it * 4 + 2] = g0 ? base[4] : 0.0f;
            ar[it * 4 + 3] = g1 ? base[(size_t)8 * K + 4] : 0.0f;
        }
    };
    auto ldgB = [&](int k0, float* br) {
        #pragma unroll
        for (int it = 0; it < 4; it++) {
            int item = it * 256 + tid;
            int kt = item >> 9, nt = (item >> 5) & 15, ln = item & 31;
            int colg = bn + nt * 8 + (ln >> 2);
            int r = k0 + kt * 8 + (ln & 3);
            bool ok = colg < N;
            const float* base = Bm + (size_t)r * ldb + colg;
            br[it * 2 + 0] = ok ? base[0] : 0.0f;
            br[it * 2 + 1] = ok ? base[(size_t)4 * ldb] : 0.0f;
        }
    };
    auto stsAB = [&](int buf, const float* ar, const float* br) {
        #pragma unroll
        for (int it = 0; it < 2; it++) {
            int item = it * 256 + tid;
            int kt = item >> 8, mt = (item >> 5) & 7, ln = item & 31;
            float4 v = make_float4(to_tf32(ar[it * 4 + 0]), to_tf32(ar[it * 4 + 1]),
                                   to_tf32(ar[it * 4 + 2]), to_tf32(ar[it * 4 + 3]));
            *(float4*)&sA[buf][((kt * 8 + mt) * 32 + (ln ^ (kt << 2))) * 4] = v;
        }
        #pragma unroll
        for (int it = 0; it < 4; it++) {
            int item = it * 256 + tid;
            int kt = item >> 9, nt = (item >> 5) & 15, ln = item & 31;
            float2 v = make_float2(to_tf32(br[it * 2 + 0]), to_tf32(br[it * 2 + 1]));
            *(float2*)&sB[buf][((kt * 16 + nt) * 32 + (ln ^ (kt << 2))) * 2] = v;
        }
    };
    auto compute = [&](int buf) {
        #pragma unroll
        for (int kt = 0; kt < 2; kt++) {
            int lx = lane ^ (kt << 2);
            float2 bf[4];
            #pragma unroll
            for (int nti = 0; nti < 4; nti++)
                bf[nti] = *(const float2*)&sB[buf][((kt * 16 + (warp_n * 4 + nti)) * 32 + lx) * 2];
            #pragma unroll
            for (int mti = 0; mti < 4; mti++) {
                float4 af = *(const float4*)&sA[buf][((kt * 8 + (warp_m * 4 + mti)) * 32 + lx) * 4];
                #pragma unroll
                for (int nti = 0; nti < 4; nti++) {
                    asm volatile(
                        "mma.sync.aligned.m16n8k8.row.col.f32.tf32.tf32.f32 "
                        "{%0,%1,%2,%3}, {%4,%5,%6,%7}, {%8,%9}, {%0,%1,%2,%3};"
                        : "+f"(acc[mti][nti][0]), "+f"(acc[mti][nti][1]),
                          "+f"(acc[mti][nti][2]), "+f"(acc[mti][nti][3])
                        : "r"(__float_as_uint(af.x)), "r"(__float_as_uint(af.y)),
                          "r"(__float_as_uint(af.z)), "r"(__float_as_uint(af.w)),
                          "r"(__float_as_uint(bf[nti].x)), "r"(__float_as_uint(bf[nti].y)));
                }
            }
        }
    };

    const int nsteps = K >> 4;
    float arA0[8], arB0[8], arA1[8], arB1[8];

    ldgA(0, arA0);  ldgB(0, arB0);
    ldgA(16, arA1); ldgB(16, arB1);
    stsAB(0, arA0, arB0);
    ldgA(32, arA0); ldgB(32, arB0);
    __syncthreads();

    int b0 = 0, b1 = 1, b2 = 2;
    int s = 0;
    while (s < nsteps) {
        compute(b0);
        if (s + 1 < nsteps) stsAB(b1, arA1, arB1);
        if (s + 3 < nsteps) { ldgA((s + 3) << 4, arA1); ldgB((s + 3) << 4, arB1); }
        __syncthreads();
        { int t = b0; b0 = b1; b1 = b2; b2 = t; }
        s++;
        if (s >= nsteps) break;
        compute(b0);
        if (s + 1 < nsteps) stsAB(b1, arA0, arB0);
        if (s + 3 < nsteps) { ldgA((s + 3) << 4, arA0); ldgB((s + 3) << 4, arB0); }
        __syncthreads();
        { int t = b0; b0 = b1; b1 = b2; b2 = t; }
        s++;
    }

    #pragma unroll
    for (int mti = 0; mti < 4; mti++) {
        #pragma unroll
        for (int r = 0; r < 4; r++) {
            int row = bm + warp_m * 64 + mti * 16 + g + ((r >= 2) ? 8 : 0);
            if (row >= M) continue;
            #pragma unroll
            for (int nti = 0; nti < 4; nti++) {
                int col = bn + warp_n * 32 + nti * 8 + tig * 2 + (r & 1);
                if (col >= N) continue;
                float v = acc[mti][nti][r];
                if (bias) v += bias[col];
                if (useVk) {
                    int kc = col - (V_ - KV_);
                    if (kc >= 0) v += g_scratch[OFF_VK + (size_t)row * KV_ + kc];
                }
                outp[(size_t)row * ldc + col] = v;
            }
        }
    }
}

// ---------------------------------------------------------------------------
// Row dot: out[m] = A[m,:K] . w + b   (warp per row). K <= 512.
// ---------------------------------------------------------------------------
__global__ void rowdot_k(long Aoff, const float* __restrict__ w,
                         const float* __restrict__ bptr, long Ooff, int M, int K) {
    __shared__ float ws[512];
    const float* A = (const float*)g_scratch + Aoff;
    float* out = g_scratch + Ooff;
    int tid = threadIdx.x;
    for (int i = tid; i < K; i += 256) ws[i] = w[i];
    __syncthreads();
    int warp = tid >> 5, lane = tid & 31;
    int row = blockIdx.x * 8 + warp;
    if (row >= M) return;
    const float* ar = A + (size_t)row * K;
    float s = 0.f;
    #pragma unroll
    for (int e = lane; e < K; e += 32) s = fmaf(ar[e], ws[e], s);
    #pragma unroll
    for (int o = 16; o; o >>= 1) s += __shfl_xor_sync(0xffffffffu, s, o);
    if (lane == 0) out[row] = s + bptr[0];
}

// ---------------------------------------------------------------------------
// softmax over L=512, in place at OFF_SC. block per b, 256 threads
// ---------------------------------------------------------------------------
__global__ void softmax_k() {
    __shared__ float red[32];
    float* row = g_scratch + OFF_SC + (size_t)blockIdx.x * L_;
    int tid = threadIdx.x;
    float v0 = row[tid], v1 = row[tid + 256];
    float m = blockReduceMax(fmaxf(v0, v1), red, tid);
    float e0 = expf(v0 - m), e1 = expf(v1 - m);
    float s = blockReduceSum(e0 + e1, red, tid);
    float inv = 1.0f / s;
    row[tid] = e0 * inv;
    row[tid + 256] = e1 * inv;
}

// ---------------------------------------------------------------------------
// h_ctx[b, col] = sum_l a[b,l] * enc[b,l,col].  grid (H/256, B)
// ---------------------------------------------------------------------------
__global__ void ctx_k(const float* __restrict__ enc) {
    __shared__ float as[L_];
    int b = blockIdx.y, tid = threadIdx.x;
    for (int i = tid; i < L_; i += 256) as[i] = g_scratch[OFF_SC + (size_t)b * L_ + i];
    __syncthreads();
    int col = blockIdx.x * 256 + tid;
    const float* ep = enc + (size_t)b * L_ * H_ + col;
    float acc = 0.f;
    #pragma unroll 4
    for (int l = 0; l < L_; l++) acc = fmaf(as[l], ep[(size_t)l * H_], acc);
    g_scratch[OFF_HCTX + (size_t)b * H_ + col] = acc;
}

// ---------------------------------------------------------------------------
// uk1[b*KV+kv, e] = tanh(bpart[b,e] + kpart[kv,e] + kb1[e])
// ---------------------------------------------------------------------------
__global__ void uk1_k(const float* __restrict__ kb1) {
    size_t idx = (size_t)blockIdx.x * 256 + threadIdx.x;   // 64*1000*512
    int e = (int)(idx & (E_ - 1));
    size_t r = idx >> 9;
    int b = (int)(r / KV_);
    int kv = (int)(r - (size_t)b * KV_);
    g_scratch[OFF_UK1 + idx] = tanhf(g_scratch[OFF_BPART + (size_t)b * E_ + e] +
                                     g_scratch[OFF_KPART + (size_t)kv * E_ + e] + kb1[e]);
}

// ---------------------------------------------------------------------------
// Acat[b, 0:2048] = cat(h_t[b], h_ctx[b])
// ---------------------------------------------------------------------------
__global__ void acat_k(const float* __restrict__ h_t) {
    int idx = blockIdx.x * 256 + threadIdx.x;   // 64*2048
    int b = idx >> 11, j = idx & 2047;
    float v = (j < H_) ? h_t[(size_t)b * H_ + j]
                       : g_scratch[OFF_HCTX + (size_t)b * H_ + (j - H_)];
    g_scratch[OFF_ACAT + idx] = v;
}

// ---------------------------------------------------------------------------
// log_softmax over V, in place on y. block per b, 1024 threads.
// ---------------------------------------------------------------------------
__global__ void logsoftmax_k(float* __restrict__ y) {
    __shared__ float red[32];
    float* row = y + (size_t)blockIdx.x * V_;
    int tid = threadIdx.x;
    float m = -INFINITY;
    for (int i = tid; i < V_; i += 1024) m = fmaxf(m, row[i]);
    m = blockReduceMax(m, red, tid);
    float s = 0.f;
    for (int i = tid; i < V_; i += 1024) s += expf(row[i] - m);
    s = blockReduceSum(s, red, tid);
    float lse = m + logf(s);
    for (int i = tid; i < V_; i += 1024) row[i] -= lse;
}

// ---------------------------------------------------------------------------
// Launch
// ---------------------------------------------------------------------------
extern "C" void kernel_launch(void* const* d_in, const int* in_sizes, int n_in,
                              void* d_out, int out_size) {
    const int*   ids  = (const int*)d_in[0];
    const float* h    = (const float*)d_in[1];
    const float* c    = (const float*)d_in[2];
    const float* k    = (const float*)d_in[3];
    const float* ctxv = (const float*)d_in[4];
    const float* enc  = (const float*)d_in[5];
    const float* emb  = (const float*)d_in[6];
    const float* W_ih = (const float*)d_in[7];
    const float* W_hh = (const float*)d_in[8];
    const float* b_ih = (const float*)d_in[9];
    const float* b_hh = (const float*)d_in[10];
    const float* aW1  = (const float*)d_in[11];
    const float* ab1  = (const float*)d_in[12];
    const float* aW2  = (const float*)d_in[13];
    const float* ab2  = (const float*)d_in[14];
    const float* aW3  = (const float*)d_in[15];
    const float* ab3  = (const float*)d_in[16];
    const float* kW1  = (const float*)d_in[17];
    const float* kb1  = (const float*)d_in[18];
    const float* kW2  = (const float*)d_in[19];
    const float* kb2  = (const float*)d_in[20];
    const float* kW3  = (const float*)d_in[21];
    const float* kb3  = (const float*)d_in[22];
    const float* alW  = (const float*)d_in[23];
    const float* alb  = (const float*)d_in[24];

    float* y   = (float*)d_out;
    float* h_t = y + (size_t)B_ * V_;
    float* c_t = h_t + (size_t)B_ * H_;

    static int smem_set = 0;
    if (!smem_set) {
        cudaFuncSetAttribute(tgemm_ca_k, cudaFuncAttributeMaxDynamicSharedMemorySize,
                             CA_SMEM_BYTES);
        smem_set = 1;
    }

    // LSTM
    gates_k<<<dim3(G4H / 256, B_), 256>>>(ids, emb, h, W_ih, W_hh, b_ih, b_hh);
    lstm_k<<<(B_ * H_) / 256, 256>>>(c, h_t, c_t);

    // additive attention:  u1 = tanh(enc@aW1[:H] + h_t@aW1[H:2H] + ab1)
    smallm_k<<<dim3(E_ / 256, B_), 256, H_ * sizeof(float)>>>(
        h_t, aW1 + (size_t)H_ * E_, OFF_HB, E_, H_, 0);
    tgemm_ca_k<<<dim3(E_ / 128, (B_ * L_) / 128), 256, CA_SMEM_BYTES>>>(
        enc, 0, aW1, E_, OFF_U1, E_,
        B_ * L_, E_, H_, ab1, 1, OFF_HB, L_, 1);
    tgemm_ca_k<<<dim3(E_ / 128, (B_ * L_) / 128), 256, CA_SMEM_BYTES>>>(
        nullptr, OFF_U1, aW2, E_, OFF_U2, E_,
        B_ * L_, E_, E_, ab2, 0, 0, 1, 1);
    rowdot_k<<<(B_ * L_) / 8, 256>>>(OFF_U2, aW3, ab3, OFF_SC, B_ * L_, E_);
    softmax_k<<<B_, 256>>>();
    ctx_k<<<dim3(H_ / 256, B_), 256>>>(enc);

    // key attention:  uk1 = tanh([ctx,h_t]@kW1[:2H] + k@kW1[2H:] + kb1)
    smallm_k<<<dim3(E_ / 256, B_), 256, H_ * sizeof(float)>>>(
        ctxv, kW1, OFF_BPART, E_, H_, 0);
    smallm_k<<<dim3(E_ / 256, B_), 256, H_ * sizeof(float)>>>(
        h_t, kW1 + (size_t)H_ * E_, OFF_BPART, E_, H_, 1);
    tgemm_ca_k<<<dim3(E_ / 128, (KV_ + 127) / 128), 256, CA_SMEM_BYTES>>>(
        k, 0, kW1 + (size_t)2 * H_ * E_, E_, OFF_KPART, E_,
        KV_, E_, E_, nullptr, 0, 0, 1, 0);
    uk1_k<<<(B_ * KV_ * E_) / 256, 256>>>(kb1);
    tgemm_ca_k<<<dim3(E_ / 128, (B_ * KV_) / 128), 256, CA_SMEM_BYTES>>>(
        nullptr, OFF_UK1, kW2, E_, OFF_UK2, E_,
        B_ * KV_, E_, E_, kb2, 0, 0, 1, 1);
    rowdot_k<<<(B_ * KV_) / 8, 256>>>(OFF_UK2, kW3, kb3, OFF_VK, B_ * KV_, E_);

    // vocab projection + key logits + log_softmax
    acat_k<<<(B_ * 2 * H_) / 256, 256>>>(h_t);
    tgemm_ldg_k<<<dim3((V_ + 127) / 128, 1), 256>>>(
        OFF_ACAT, alW, V_, y, V_,
        B_, V_, 2 * H_, alb, 1);
    logsoftmax_k<<<B_, 1024>>>(y);
}

// round 9
// speedup vs baseline: 1.6949x; 1.2051x over previous
#include <cuda_runtime.h>
#include <math.h>
#include <stdint.h>

// ---------------------------------------------------------------------------
// Problem constants
// ---------------------------------------------------------------------------
constexpr int B_  = 64;
constexpr int H_  = 1024;
constexpr int E_  = 512;
constexpr int V_  = 50257;
constexpr int KV_ = 1000;
constexpr int L_  = 512;
constexpr int G4H = 4 * H_;   // 4096

// ---------------------------------------------------------------------------
// Scratch arena (static device global: allocation-free per harness rules)
// ---------------------------------------------------------------------------
constexpr long OFF_GATES = 0;
constexpr long OFF_HB    = OFF_GATES + (long)B_ * G4H;
constexpr long OFF_U1    = OFF_HB    + (long)B_ * E_;
constexpr long OFF_U2    = OFF_U1    + (long)B_ * L_ * E_;
constexpr long OFF_SC    = OFF_U2    + (long)B_ * L_ * E_;
constexpr long OFF_HCTX  = OFF_SC    + (long)B_ * L_;
constexpr long OFF_KPART = OFF_HCTX  + (long)B_ * H_;
constexpr long OFF_BPART = OFF_KPART + (long)KV_ * E_;
constexpr long OFF_UK1   = OFF_BPART + (long)B_ * E_;
constexpr long OFF_UK2   = OFF_UK1   + (long)B_ * KV_ * E_;
constexpr long OFF_VK    = OFF_UK2   + (long)B_ * KV_ * E_;
constexpr long OFF_ACAT  = OFF_VK    + (long)B_ * KV_;
constexpr long SCRATCH_TOTAL = OFF_ACAT + (long)B_ * 2 * H_;

__device__ __align__(16) float g_scratch[SCRATCH_TOTAL];

// ---------------------------------------------------------------------------
// Helpers
// ---------------------------------------------------------------------------
static __device__ __forceinline__ float sigmoidf_(float x) {
    return 1.0f / (1.0f + expf(-x));
}

static __device__ __forceinline__ uint32_t smem_u32(const void* p) {
    return (uint32_t)__cvta_generic_to_shared(p);
}

static __device__ __forceinline__ void cp_async16(uint32_t dst, const void* src, int szBytes) {
    asm volatile("cp.async.cg.shared.global [%0], [%1], 16, %2;\n"
                 :: "r"(dst), "l"(src), "r"(szBytes) : "memory");
}

static __device__ __forceinline__ void cp_async4(uint32_t dst, const void* src, int szBytes) {
    asm volatile("cp.async.ca.shared.global [%0], [%1], 4, %2;\n"
                 :: "r"(dst), "l"(src), "r"(szBytes) : "memory");
}

static __device__ __forceinline__ float blockReduceMax(float v, float* red, int tid) {
    #pragma unroll
    for (int o = 16; o; o >>= 1) v = fmaxf(v, __shfl_xor_sync(0xffffffffu, v, o));
    if ((tid & 31) == 0) red[tid >> 5] = v;
    __syncthreads();
    int nw = blockDim.x >> 5;
    float r = red[0];
    for (int i = 1; i < nw; i++) r = fmaxf(r, red[i]);
    __syncthreads();
    return r;
}

static __device__ __forceinline__ float blockReduceSum(float v, float* red, int tid) {
    #pragma unroll
    for (int o = 16; o; o >>= 1) v += __shfl_xor_sync(0xffffffffu, v, o);
    if ((tid & 31) == 0) red[tid >> 5] = v;
    __syncthreads();
    int nw = blockDim.x >> 5;
    float r = red[0];
    for (int i = 1; i < nw; i++) r += red[i];
    __syncthreads();
    return r;
}

// ---------------------------------------------------------------------------
// K1: LSTM gates = emb[ids] @ W_ih + h @ W_hh + b_ih + b_hh
// ---------------------------------------------------------------------------
__global__ void gates_k(const int* __restrict__ ids, const float* __restrict__ emb,
                        const float* __restrict__ h, const float* __restrict__ W_ih,
                        const float* __restrict__ W_hh, const float* __restrict__ b_ih,
                        const float* __restrict__ b_hh) {
    __shared__ float xs[E_];
    __shared__ float hs[H_];
    int b = blockIdx.y;
    int tid = threadIdx.x;
    long er = (long)ids[b] * E_;
    for (int i = tid; i < E_; i += 256) xs[i] = emb[er + i];
    for (int i = tid; i < H_; i += 256) hs[i] = h[(size_t)b * H_ + i];
    __syncthreads();
    int col = blockIdx.x * 256 + tid;
    float acc = b_ih[col] + b_hh[col];
    #pragma unroll 4
    for (int e = 0; e < E_; e++) acc = fmaf(xs[e], W_ih[(size_t)e * G4H + col], acc);
    #pragma unroll 4
    for (int e = 0; e < H_; e++) acc = fmaf(hs[e], W_hh[(size_t)e * G4H + col], acc);
    g_scratch[OFF_GATES + (size_t)b * G4H + col] = acc;
}

// ---------------------------------------------------------------------------
// K2: LSTM elementwise (gate order i, f, g, o)
// ---------------------------------------------------------------------------
__global__ void lstm_k(const float* __restrict__ c_in,
                       float* __restrict__ h_t, float* __restrict__ c_t) {
    int idx = blockIdx.x * 256 + threadIdx.x;      // B*H = 65536
    int b = idx >> 10, j = idx & 1023;
    const float* g = g_scratch + OFF_GATES + (size_t)b * G4H;
    float ig = sigmoidf_(g[j]);
    float fg = sigmoidf_(g[H_ + j]);
    float gg = tanhf(g[2 * H_ + j]);
    float og = sigmoidf_(g[3 * H_ + j]);
    float ct = fg * c_in[idx] + ig * gg;
    c_t[idx] = ct;
    h_t[idx] = og * tanhf(ct);
}

// ---------------------------------------------------------------------------
// Small-M GEMM: one row per blockIdx.y (M<=64). C (scratch) = A[m,:] @ B (+C)
// ---------------------------------------------------------------------------
__global__ void smallm_k(const float* __restrict__ A, const float* __restrict__ Bm,
                         long Coff, int N, int K, int accumulate) {
    extern __shared__ float As[];
    float* C = g_scratch + Coff;
    int m = blockIdx.y;
    for (int i = threadIdx.x; i < K; i += blockDim.x) As[i] = A[(size_t)m * K + i];
    __syncthreads();
    int col = blockIdx.x * blockDim.x + threadIdx.x;
    float acc = accumulate ? C[(size_t)m * N + col] : 0.0f;
    #pragma unroll 4
    for (int kk = 0; kk < K; kk++)
        acc = fmaf(As[kk], Bm[(size_t)kk * N + col], acc);
    C[(size_t)m * N + col] = acc;
}

// ---------------------------------------------------------------------------
// TF32 tensor-core GEMM with 4-stage cp.async pipeline.
// CTA tile 128x128, k-step 16, 8 warps of 64x32 (m16n8k8 mma).
// A smem: [128 rows][stride 20 floats]; B smem: [16 k][128 n], 8-float XOR
// swizzle (n>>3)^(k&3). HMMA.TF32 truncates mantissa in HW (no cvt needed).
// Requires: K%16==0, N multiple of 128, ldb%4==0, A rows 16B-aligned.
// ---------------------------------------------------------------------------
constexpr int CA_ASTRIDE = 20;
constexpr int CA_ASZ = 128 * CA_ASTRIDE;          // 2560 floats / stage
constexpr int CA_BSZ = 16 * 128;                  // 2048 floats / stage
constexpr int CA_STAGES = 4;
constexpr int CA_SMEM_BYTES = CA_STAGES * (CA_ASZ + CA_BSZ) * 4;   // 73728 B

__global__ __launch_bounds__(256, 2) void tgemm_ca_k(
    const float* __restrict__ Ap, long Aoff,
    const float* __restrict__ Bm, int ldb,
    long Coff, int ldc,
    int M, int N, int K,
    const float* __restrict__ bias,
    int useRowAdd, long rowAddOff, int rowDiv,
    int doTanh) {

    extern __shared__ float smem[];
    float* Abase = smem;
    float* Bbase = smem + CA_STAGES * CA_ASZ;

    const float* A = Ap ? Ap : (const float*)g_scratch + Aoff;

    const int tid  = threadIdx.x;
    const int wid  = tid >> 5;
    const int lane = tid & 31;
    const int warp_m = wid & 1;
    const int warp_n = wid >> 1;
    const int g   = lane >> 2;
    const int tig = lane & 3;

    const int bm = blockIdx.y * 128;
    const int bn = blockIdx.x * 128;
    const int nsteps = K >> 4;

    float acc[4][4][4];
    #pragma unroll
    for (int i = 0; i < 4; i++)
        #pragma unroll
        for (int j = 0; j < 4; j++)
            #pragma unroll
            for (int r = 0; r < 4; r++) acc[i][j][r] = 0.0f;

    const int aRow0 = tid >> 2;
    const int aC    = (tid & 3) * 4;
    const int bK0   = tid >> 5;
    const int bCn   = tid & 31;

    auto issue = [&](int buf, int kstep) {
        if (kstep < nsteps) {
            const int k0 = kstep << 4;
            float* Ad = Abase + buf * CA_ASZ;
            float* Bd = Bbase + buf * CA_BSZ;
            #pragma unroll
            for (int it = 0; it < 2; it++) {
                int row = aRow0 + it * 64;
                int rg = bm + row;
                int ok = rg < M;
                int rc = ok ? rg : (M - 1);
                cp_async16(smem_u32(Ad + row * CA_ASTRIDE + aC),
                           A + (size_t)rc * K + k0 + aC, ok ? 16 : 0);
            }
            #pragma unroll
            for (int it = 0; it < 2; it++) {
                int kr = bK0 + it * 8;
                uint32_t grp = (uint32_t)(bCn >> 1) ^ (uint32_t)(kr & 3);
                cp_async16(smem_u32(Bd + kr * 128 + grp * 8 + (bCn & 1) * 4),
                           Bm + (size_t)(k0 + kr) * ldb + bn + bCn * 4, 16);
            }
        }
        asm volatile("cp.async.commit_group;\n" ::: "memory");
    };

    int bcol[4];
    #pragma unroll
    for (int nti = 0; nti < 4; nti++)
        bcol[nti] = g + 8 * ((warp_n * 4 + nti) ^ tig);
    const int am0 = (warp_m * 64 + g) * CA_ASTRIDE;

    auto compute = [&](int buf) {
        const float* At = Abase + buf * CA_ASZ;
        const float* Bt = Bbase + buf * CA_BSZ;
        #pragma unroll
        for (int kt = 0; kt < 2; kt++) {
            const int k0 = kt * 8 + tig;
            float b0[4], b1[4];
            #pragma unroll
            for (int nti = 0; nti < 4; nti++) {
                b0[nti] = Bt[k0 * 128 + bcol[nti]];
                b1[nti] = Bt[(k0 + 4) * 128 + bcol[nti]];
            }
            #pragma unroll
            for (int mti = 0; mti < 4; mti++) {
                const float* Ar = At + am0 + mti * 16 * CA_ASTRIDE;
                float a0 = Ar[k0];
                float a1 = Ar[8 * CA_ASTRIDE + k0];
                float a2 = Ar[k0 + 4];
                float a3 = Ar[8 * CA_ASTRIDE + k0 + 4];
                #pragma unroll
                for (int nti = 0; nti < 4; nti++) {
                    asm volatile(
                        "mma.sync.aligned.m16n8k8.row.col.f32.tf32.tf32.f32 "
                        "{%0,%1,%2,%3}, {%4,%5,%6,%7}, {%8,%9}, {%0,%1,%2,%3};"
                        : "+f"(acc[mti][nti][0]), "+f"(acc[mti][nti][1]),
                          "+f"(acc[mti][nti][2]), "+f"(acc[mti][nti][3])
                        : "r"(__float_as_uint(a0)), "r"(__float_as_uint(a1)),
                          "r"(__float_as_uint(a2)), "r"(__float_as_uint(a3)),
                          "r"(__float_as_uint(b0[nti])), "r"(__float_as_uint(b1[nti])));
                }
            }
        }
    };

    issue(0, 0);
    issue(1, 1);
    issue(2, 2);

    for (int s = 0; s < nsteps; s++) {
        asm volatile("cp.async.wait_group 2;\n" ::: "memory");
        __syncthreads();
        int nb = s + 3;
        issue(nb & 3, nb);
        compute(s & 3);
    }

    float* Co = g_scratch + Coff;
    const float* raB = useRowAdd ? (const float*)g_scratch + rowAddOff : nullptr;
    #pragma unroll
    for (int mti = 0; mti < 4; mti++) {
        #pragma unroll
        for (int r = 0; r < 4; r++) {
            int row = bm + warp_m * 64 + mti * 16 + g + ((r >= 2) ? 8 : 0);
            if (row >= M) continue;
            const float* ra = raB ? raB + (size_t)(row / rowDiv) * N : nullptr;
            #pragma unroll
            for (int nti = 0; nti < 4; nti++) {
                int col = bn + warp_n * 32 + nti * 8 + tig * 2 + (r & 1);
                float v = acc[mti][nti][r];
                if (bias) v += bias[col];
                if (ra) v += ra[col];
                if (doTanh) v = tanhf(v);
                Co[(size_t)row * ldc + col] = v;
            }
        }
    }
}

// ---------------------------------------------------------------------------
// Vocab GEMM: y[64, V] = Acat[64, 2048] @ alW[2048, V] + alb + vk pad.
// M tile = 64 (exact), N tile = 256 -> grid 197 = one wave @ 2 CTA/SM.
// 8 warps each compute 64x32. B streamed via 4-byte cp.async (ldb=V odd),
// coalesced along n; 4-stage pipeline (80KB in flight) hides DRAM latency.
// Memory-bound by the 411MB alW stream.
// ---------------------------------------------------------------------------
constexpr int VG_ASTRIDE = 20;
constexpr int VG_ASZ = 64 * VG_ASTRIDE;     // 1280 floats / stage
constexpr int VG_BSZ = 16 * 256;            // 4096 floats / stage
constexpr int VG_STAGES = 4;
constexpr int VG_SMEM_BYTES = VG_STAGES * (VG_ASZ + VG_BSZ) * 4;  // 86016 B
constexpr int VG_NSTEPS = (2 * H_) / 16;    // 128

__global__ __launch_bounds__(256, 2) void vgemm_k(
    const float* __restrict__ Bm,      // alW [2048, V]
    const float* __restrict__ bias,    // alb
    float* __restrict__ y) {

    extern __shared__ float smem[];
    float* Abase = smem;
    float* Bbase = smem + VG_STAGES * VG_ASZ;

    const float* A = (const float*)g_scratch + OFF_ACAT;   // [64, 2048]

    const int tid  = threadIdx.x;
    const int wid  = tid >> 5;
    const int lane = tid & 31;
    const int g    = lane >> 2;
    const int tig  = lane & 3;

    const int bn = blockIdx.x * 256;

    float acc[4][4][4];
    #pragma unroll
    for (int i = 0; i < 4; i++)
        #pragma unroll
        for (int j = 0; j < 4; j++)
            #pragma unroll
            for (int r = 0; r < 4; r++) acc[i][j][r] = 0.0f;

    const int aRow = tid >> 2;          // 0..63
    const int aC   = (tid & 3) * 4;
    const int nCol = bn + tid;          // this thread's B column
    const int colOk = (nCol < V_) ? 4 : 0;
    const int nColC = (nCol < V_) ? nCol : (V_ - 1);
    const uint32_t bDstOff = (uint32_t)(((tid >> 3) * 8) * 0 + 0);  // computed per it below

    auto issue = [&](int buf, int kstep) {
        if (kstep < VG_NSTEPS) {
            const int k0 = kstep << 4;
            float* Ad = Abase + buf * VG_ASZ;
            float* Bd = Bbase + buf * VG_BSZ;
            cp_async16(smem_u32(Ad + aRow * VG_ASTRIDE + aC),
                       A + (size_t)aRow * 2048 + k0 + aC, 16);
            const float* src = Bm + (size_t)k0 * V_ + nColC;
            #pragma unroll
            for (int it = 0; it < 16; it++) {
                // element (k = it, n = tid); swizzled dst block = (n>>3)^(k&3)
                uint32_t dpos = (uint32_t)it * 256
                              + (((uint32_t)(tid >> 3) ^ (uint32_t)(it & 3)) * 8)
                              + (uint32_t)(tid & 7);
                cp_async4(smem_u32(Bd + dpos), src + (size_t)it * V_, colOk);
            }
        }
        asm volatile("cp.async.commit_group;\n" ::: "memory");
    };

    int bcol[4];
    #pragma unroll
    for (int nti = 0; nti < 4; nti++)
        bcol[nti] = g + 8 * ((wid * 4 + nti) ^ tig);
    const int am0 = g * VG_ASTRIDE;

    auto compute = [&](int buf) {
        const float* At = Abase + buf * VG_ASZ;
        const float* Bt = Bbase + buf * VG_BSZ;
        #pragma unroll
        for (int kt = 0; kt < 2; kt++) {
            const int k0 = kt * 8 + tig;
            float b0[4], b1[4];
            #pragma unroll
            for (int nti = 0; nti < 4; nti++) {
                b0[nti] = Bt[k0 * 256 + bcol[nti]];
                b1[nti] = Bt[(k0 + 4) * 256 + bcol[nti]];
            }
            #pragma unroll
            for (int mti = 0; mti < 4; mti++) {
                const float* Ar = At + am0 + mti * 16 * VG_ASTRIDE;
                float a0 = Ar[k0];
                float a1 = Ar[8 * VG_ASTRIDE + k0];
                float a2 = Ar[k0 + 4];
                float a3 = Ar[8 * VG_ASTRIDE + k0 + 4];
                #pragma unroll
                for (int nti = 0; nti < 4; nti++) {
                    asm volatile(
                        "mma.sync.aligned.m16n8k8.row.col.f32.tf32.tf32.f32 "
                        "{%0,%1,%2,%3}, {%4,%5,%6,%7}, {%8,%9}, {%0,%1,%2,%3};"
                        : "+f"(acc[mti][nti][0]), "+f"(acc[mti][nti][1]),
                          "+f"(acc[mti][nti][2]), "+f"(acc[mti][nti][3])
                        : "r"(__float_as_uint(a0)), "r"(__float_as_uint(a1)),
                          "r"(__float_as_uint(a2)), "r"(__float_as_uint(a3)),
                          "r"(__float_as_uint(b0[nti])), "r"(__float_as_uint(b1[nti])));
                }
            }
        }
    };

    issue(0, 0);
    issue(1, 1);
    issue(2, 2);

    for (int s = 0; s < VG_NSTEPS; s++) {
        asm volatile("cp.async.wait_group 2;\n" ::: "memory");
        __syncthreads();
        int nb = s + 3;
        issue(nb & 3, nb);
        compute(s & 3);
    }

    #pragma unroll
    for (int mti = 0; mti < 4; mti++) {
        #pragma unroll
        for (int r = 0; r < 4; r++) {
            int row = mti * 16 + g + ((r >= 2) ? 8 : 0);   // 0..63
            #pragma unroll
            for (int nti = 0; nti < 4; nti++) {
                int col = bn + wid * 32 + nti * 8 + tig * 2 + (r & 1);
                if (col >= V_) continue;
                float v = acc[mti][nti][r] + bias[col];
                int kc = col - (V_ - KV_);
                if (kc >= 0) v += g_scratch[OFF_VK + (size_t)row * KV_ + kc];
                y[(size_t)row * V_ + col] = v;
            }
        }
    }
}

// ---------------------------------------------------------------------------
// Row dot: out[m] = A[m,:K] . w + b   (warp per row). K <= 512.
// ---------------------------------------------------------------------------
__global__ void rowdot_k(long Aoff, const float* __restrict__ w,
                         const float* __restrict__ bptr, long Ooff, int M, int K) {
    __shared__ float ws[512];
    const float* A = (const float*)g_scratch + Aoff;
    float* out = g_scratch + Ooff;
    int tid = threadIdx.x;
    for (int i = tid; i < K; i += 256) ws[i] = w[i];
    __syncthreads();
    int warp = tid >> 5, lane = tid & 31;
    int row = blockIdx.x * 8 + warp;
    if (row >= M) return;
    const float* ar = A + (size_t)row * K;
    float s = 0.f;
    #pragma unroll
    for (int e = lane; e < K; e += 32) s = fmaf(ar[e], ws[e], s);
    #pragma unroll
    for (int o = 16; o; o >>= 1) s += __shfl_xor_sync(0xffffffffu, s, o);
    if (lane == 0) out[row] = s + bptr[0];
}

// ---------------------------------------------------------------------------
// softmax over L=512, in place at OFF_SC. block per b, 256 threads
// ---------------------------------------------------------------------------
__global__ void softmax_k() {
    __shared__ float red[32];
    float* row = g_scratch + OFF_SC + (size_t)blockIdx.x * L_;
    int tid = threadIdx.x;
    float v0 = row[tid], v1 = row[tid + 256];
    float m = blockReduceMax(fmaxf(v0, v1), red, tid);
    float e0 = expf(v0 - m), e1 = expf(v1 - m);
    float s = blockReduceSum(e0 + e1, red, tid);
    float inv = 1.0f / s;
    row[tid] = e0 * inv;
    row[tid + 256] = e1 * inv;
}

// ---------------------------------------------------------------------------
// h_ctx[b, col] = sum_l a[b,l] * enc[b,l,col].  grid (H/256, B)
// ---------------------------------------------------------------------------
__global__ void ctx_k(const float* __restrict__ enc) {
    __shared__ float as[L_];
    int b = blockIdx.y, tid = threadIdx.x;
    for (int i = tid; i < L_; i += 256) as[i] = g_scratch[OFF_SC + (size_t)b * L_ + i];
    __syncthreads();
    int col = blockIdx.x * 256 + tid;
    const float* ep = enc + (size_t)b * L_ * H_ + col;
    float acc = 0.f;
    #pragma unroll 4
    for (int l = 0; l < L_; l++) acc = fmaf(as[l], ep[(size_t)l * H_], acc);
    g_scratch[OFF_HCTX + (size_t)b * H_ + col] = acc;
}

// ---------------------------------------------------------------------------
// uk1[b*KV+kv, e4] = tanh(bpart[b] + kpart[kv] + kb1), float4 per thread
// ---------------------------------------------------------------------------
__global__ void uk1_k(const float* __restrict__ kb1) {
    size_t idx = (size_t)blockIdx.x * 256 + threadIdx.x;   // 64*1000*128 items
    int e4 = (int)(idx & 127) * 4;
    size_t r = idx >> 7;
    int b = (int)(r / KV_);
    int kv = (int)(r - (size_t)b * KV_);
    float4 bp = *(const float4*)(g_scratch + OFF_BPART + (size_t)b * E_ + e4);
    float4 kp = *(const float4*)(g_scratch + OFF_KPART + (size_t)kv * E_ + e4);
    float4 kb = *(const float4*)(kb1 + e4);
    float4 o;
    o.x = tanhf(bp.x + kp.x + kb.x);
    o.y = tanhf(bp.y + kp.y + kb.y);
    o.z = tanhf(bp.z + kp.z + kb.z);
    o.w = tanhf(bp.w + kp.w + kb.w);
    *(float4*)(g_scratch + OFF_UK1 + r * E_ + e4) = o;
}

// ---------------------------------------------------------------------------
// Acat[b, 0:2048] = cat(h_t[b], h_ctx[b])
// ---------------------------------------------------------------------------
__global__ void acat_k(const float* __restrict__ h_t) {
    int idx = blockIdx.x * 256 + threadIdx.x;   // 64*2048
    int b = idx >> 11, j = idx & 2047;
    float v = (j < H_) ? h_t[(size_t)b * H_ + j]
                       : g_scratch[OFF_HCTX + (size_t)b * H_ + (j - H_)];
    g_scratch[OFF_ACAT + idx] = v;
}

// ---------------------------------------------------------------------------
// log_softmax over V, in place on y. block per b, 1024 threads.
// ---------------------------------------------------------------------------
__global__ void logsoftmax_k(float* __restrict__ y) {
    __shared__ float red[32];
    float* row = y + (size_t)blockIdx.x * V_;
    int tid = threadIdx.x;
    float m = -INFINITY;
    for (int i = tid; i < V_; i += 1024) m = fmaxf(m, row[i]);
    m = blockReduceMax(m, red, tid);
    float s = 0.f;
    for (int i = tid; i < V_; i += 1024) s += expf(row[i] - m);
    s = blockReduceSum(s, red, tid);
    float lse = m + logf(s);
    for (int i = tid; i < V_; i += 1024) row[i] -= lse;
}

// ---------------------------------------------------------------------------
// Launch
// ---------------------------------------------------------------------------
extern "C" void kernel_launch(void* const* d_in, const int* in_sizes, int n_in,
                              void* d_out, int out_size) {
    const int*   ids  = (const int*)d_in[0];
    const float* h    = (const float*)d_in[1];
    const float* c    = (const float*)d_in[2];
    const float* k    = (const float*)d_in[3];
    const float* ctxv = (const float*)d_in[4];
    const float* enc  = (const float*)d_in[5];
    const float* emb  = (const float*)d_in[6];
    const float* W_ih = (const float*)d_in[7];
    const float* W_hh = (const float*)d_in[8];
    const float* b_ih = (const float*)d_in[9];
    const float* b_hh = (const float*)d_in[10];
    const float* aW1  = (const float*)d_in[11];
    const float* ab1  = (const float*)d_in[12];
    const float* aW2  = (const float*)d_in[13];
    const float* ab2  = (const float*)d_in[14];
    const float* aW3  = (const float*)d_in[15];
    const float* ab3  = (const float*)d_in[16];
    const float* kW1  = (const float*)d_in[17];
    const float* kb1  = (const float*)d_in[18];
    const float* kW2  = (const float*)d_in[19];
    const float* kb2  = (const float*)d_in[20];
    const float* kW3  = (const float*)d_in[21];
    const float* kb3  = (const float*)d_in[22];
    const float* alW  = (const float*)d_in[23];
    const float* alb  = (const float*)d_in[24];

    float* y   = (float*)d_out;
    float* h_t = y + (size_t)B_ * V_;
    float* c_t = h_t + (size_t)B_ * H_;

    static int smem_set = 0;
    if (!smem_set) {
        cudaFuncSetAttribute(tgemm_ca_k, cudaFuncAttributeMaxDynamicSharedMemorySize,
                             CA_SMEM_BYTES);
        cudaFuncSetAttribute(vgemm_k, cudaFuncAttributeMaxDynamicSharedMemorySize,
                             VG_SMEM_BYTES);
        smem_set = 1;
    }

    // LSTM
    gates_k<<<dim3(G4H / 256, B_), 256>>>(ids, emb, h, W_ih, W_hh, b_ih, b_hh);
    lstm_k<<<(B_ * H_) / 256, 256>>>(c, h_t, c_t);

    // additive attention:  u1 = tanh(enc@aW1[:H] + h_t@aW1[H:2H] + ab1)
    smallm_k<<<dim3(E_ / 256, B_), 256, H_ * sizeof(float)>>>(
        h_t, aW1 + (size_t)H_ * E_, OFF_HB, E_, H_, 0);
    tgemm_ca_k<<<dim3(E_ / 128, (B_ * L_) / 128), 256, CA_SMEM_BYTES>>>(
        enc, 0, aW1, E_, OFF_U1, E_,
        B_ * L_, E_, H_, ab1, 1, OFF_HB, L_, 1);
    tgemm_ca_k<<<dim3(E_ / 128, (B_ * L_) / 128), 256, CA_SMEM_BYTES>>>(
        nullptr, OFF_U1, aW2, E_, OFF_U2, E_,
        B_ * L_, E_, E_, ab2, 0, 0, 1, 1);
    rowdot_k<<<(B_ * L_) / 8, 256>>>(OFF_U2, aW3, ab3, OFF_SC, B_ * L_, E_);
    softmax_k<<<B_, 256>>>();
    ctx_k<<<dim3(H_ / 256, B_), 256>>>(enc);

    // key attention:  uk1 = tanh([ctx,h_t]@kW1[:2H] + k@kW1[2H:] + kb1)
    smallm_k<<<dim3(E_ / 256, B_), 256, H_ * sizeof(float)>>>(
        ctxv, kW1, OFF_BPART, E_, H_, 0);
    smallm_k<<<dim3(E_ / 256, B_), 256, H_ * sizeof(float)>>>(
        h_t, kW1 + (size_t)H_ * E_, OFF_BPART, E_, H_, 1);
    tgemm_ca_k<<<dim3(E_ / 128, (KV_ + 127) / 128), 256, CA_SMEM_BYTES>>>(
        k, 0, kW1 + (size_t)2 * H_ * E_, E_, OFF_KPART, E_,
        KV_, E_, E_, nullptr, 0, 0, 1, 0);
    uk1_k<<<(B_ * KV_ * E_ / 4) / 256, 256>>>(kb1);
    tgemm_ca_k<<<dim3(E_ / 128, (B_ * KV_) / 128), 256, CA_SMEM_BYTES>>>(
        nullptr, OFF_UK1, kW2, E_, OFF_UK2, E_,
        B_ * KV_, E_, E_, kb2, 0, 0, 1, 1);
    rowdot_k<<<(B_ * KV_) / 8, 256>>>(OFF_UK2, kW3, kb3, OFF_VK, B_ * KV_, E_);

    // vocab projection + key logits + log_softmax
    acat_k<<<(B_ * 2 * H_) / 256, 256>>>(h_t);
    vgemm_k<<<(V_ + 255) / 256, 256, VG_SMEM_BYTES>>>(alW, alb, y);
    logsoftmax_k<<<B_, 1024>>>(y);
}